// round 4
// baseline (speedup 1.0000x reference)
#include <cuda_runtime.h>
#include <cuda_bf16.h>

// ---------------------------------------------------------------------------
// Net_67765993996461  R4: 256-n conv tiles (1 CTA/SM, double-buffered),
// vectorized LIF (4-m per thread), lif3+tsum fusion, windowed conv1.
// ---------------------------------------------------------------------------

#define TAUF ((float)(10.0 / 7.0))

constexpr int BB   = 32;
constexpr int CC   = 64;
constexpr int TT_  = 129;
constexpr int TIN  = 128;
constexpr int MM   = 40;
constexpr int N_SP = TT_ * MM;        // 5160
constexpr int VOL   = BB * CC * N_SP;
constexpr int VTHREADS = BB * CC * (MM / 4);   // 20480 (4-m vector lanes)

constexpr int NT = 256;   // conv n-tile
constexpr int AP = 72;    // As row stride: 9*16B -> LDSM conflict-free
constexpr int BP = 264;   // Bs row stride: 33*16B -> LDSM conflict-free
constexpr int A_ELEMS = 192 * AP;          // per buffer
constexpr int B_ELEMS = 64 * BP;           // per buffer
constexpr int SMEM_BYTES = (2 * A_ELEMS + 2 * B_ELEMS) * 2;  // 122880

// Scratch
__device__ __nv_bfloat16 g_s1[VOL];
__device__ float         g_u [VOL];
__device__ __nv_bfloat16 g_s2[VOL];
__device__ __nv_bfloat16 g_w2s[12 * 3 * CC * CC];  // [tap][split][co][ci]
__device__ __nv_bfloat16 g_w3s[12 * 3 * CC * CC];
__device__ float         g_ssum[BB * CC * MM];

// ---------------------------------------------------------------------------
// conv1 + LIF, vectorized: thread -> (b, c, m4), register row window.
// ---------------------------------------------------------------------------
__global__ void conv1_lif_kernel(const float* __restrict__ x,
                                 const float* __restrict__ w1) {
    int idx = blockIdx.x * blockDim.x + threadIdx.x;
    if (idx >= VTHREADS) return;
    int mq = idx % 10;
    int c  = (idx / 10) % CC;
    int b  = idx / (10 * CC);
    int m4 = mq * 4;

    float w[12];
#pragma unroll
    for (int k = 0; k < 12; k++) w[k] = w1[c * 12 + k];

    const float* xb = x + (size_t)b * TIN * MM;

    float r0[6], r1[6], r2[6], r3[6];
    auto load_row = [&](float* d, int t) {
        if (t >= 0 && t < TIN) {
            float4 cv = *(const float4*)(xb + t * MM + m4);
            d[1] = cv.x; d[2] = cv.y; d[3] = cv.z; d[4] = cv.w;
            d[0] = (m4 > 0)       ? xb[t * MM + m4 - 1] : 0.f;
            d[5] = (m4 + 4 < MM)  ? xb[t * MM + m4 + 4] : 0.f;
        } else {
#pragma unroll
            for (int j = 0; j < 6; j++) d[j] = 0.f;
        }
    };
#pragma unroll
    for (int j = 0; j < 6; j++) { r0[j] = 0.f; r1[j] = 0.f; }
    load_row(r2, 0);
    load_row(r3, 1);

    __nv_bfloat16* sp = g_s1 + (size_t)(b * CC + c) * N_SP + m4;
    float v0 = 0.f, v1 = 0.f, v2 = 0.f, v3 = 0.f;

    for (int t = 0; t < TT_; t++) {
        float u[4];
#pragma unroll
        for (int j = 0; j < 4; j++) {
            float s = 0.f;
#pragma unroll
            for (int km = 0; km < 3; km++) {
                s += w[0 * 3 + km] * r0[j + km];
                s += w[1 * 3 + km] * r1[j + km];
                s += w[2 * 3 + km] * r2[j + km];
                s += w[3 * 3 + km] * r3[j + km];
            }
            u[j] = s;
        }
        v0 = v0 + (u[0] - v0) / TAUF;
        v1 = v1 + (u[1] - v1) / TAUF;
        v2 = v2 + (u[2] - v2) / TAUF;
        v3 = v3 + (u[3] - v3) / TAUF;
        float s0 = (v0 >= 1.f) ? 1.f : 0.f;
        float s1 = (v1 >= 1.f) ? 1.f : 0.f;
        float s2 = (v2 >= 1.f) ? 1.f : 0.f;
        float s3 = (v3 >= 1.f) ? 1.f : 0.f;
        v0 = (v0 >= 1.f) ? 0.f : v0;
        v1 = (v1 >= 1.f) ? 0.f : v1;
        v2 = (v2 >= 1.f) ? 0.f : v2;
        v3 = (v3 >= 1.f) ? 0.f : v3;
        __nv_bfloat162 h01 = __floats2bfloat162_rn(s0, s1);
        __nv_bfloat162 h23 = __floats2bfloat162_rn(s2, s3);
        uint2 o = make_uint2(*(unsigned*)&h01, *(unsigned*)&h23);
        *(uint2*)(sp + t * MM) = o;

#pragma unroll
        for (int j = 0; j < 6; j++) { r0[j] = r1[j]; r1[j] = r2[j]; r2[j] = r3[j]; }
        load_row(r3, t + 2);
    }
}

// ---------------------------------------------------------------------------
// Exact 3-way bf16 split, layout [tap][split][co][ci]
// ---------------------------------------------------------------------------
__global__ void wsplit_kernel(const float* __restrict__ w, int which) {
    __nv_bfloat16* ws = which ? g_w3s : g_w2s;
    int i = blockIdx.x * blockDim.x + threadIdx.x;   // i = co*768 + ci*12 + tap
    if (i >= CC * CC * 12) return;
    int co  = i / 768;
    int r   = i - co * 768;
    int ci  = r / 12;
    int tap = r - ci * 12;
    float v = w[i];
    __nv_bfloat16 h0 = __float2bfloat16_rz(v);
    float r1 = v - __bfloat162float(h0);
    __nv_bfloat16 h1 = __float2bfloat16_rz(r1);
    float r2 = r1 - __bfloat162float(h1);
    __nv_bfloat16 h2 = __float2bfloat16_rz(r2);
    ws[((tap * 3 + 0) * CC + co) * CC + ci] = h0;
    ws[((tap * 3 + 1) * CC + co) * CC + ci] = h1;
    ws[((tap * 3 + 2) * CC + co) * CC + ci] = h2;
}

// ---------------------------------------------------------------------------
__device__ __forceinline__ void mma16816(float* d, const unsigned* a, const unsigned* b) {
    asm volatile(
        "mma.sync.aligned.m16n8k16.row.col.f32.bf16.bf16.f32 "
        "{%0,%1,%2,%3}, {%4,%5,%6,%7}, {%8,%9}, {%0,%1,%2,%3};\n"
        : "+f"(d[0]), "+f"(d[1]), "+f"(d[2]), "+f"(d[3])
        : "r"(a[0]), "r"(a[1]), "r"(a[2]), "r"(a[3]), "r"(b[0]), "r"(b[1]));
}
__device__ __forceinline__ void ldsm_x4(unsigned addr, unsigned& r0, unsigned& r1,
                                        unsigned& r2, unsigned& r3) {
    asm volatile("ldmatrix.sync.aligned.m8n8.x4.shared.b16 {%0,%1,%2,%3}, [%4];\n"
                 : "=r"(r0), "=r"(r1), "=r"(r2), "=r"(r3) : "r"(addr));
}
__device__ __forceinline__ void ldsm_x4_t(unsigned addr, unsigned& r0, unsigned& r1,
                                          unsigned& r2, unsigned& r3) {
    asm volatile("ldmatrix.sync.aligned.m8n8.x4.trans.shared.b16 {%0,%1,%2,%3}, [%4];\n"
                 : "=r"(r0), "=r"(r1), "=r"(r2), "=r"(r3) : "r"(addr));
}
__device__ __forceinline__ unsigned smem_u32(const void* p) {
    return (unsigned)__cvta_generic_to_shared(p);
}

// ---------------------------------------------------------------------------
// Tap-decomposed conv GEMM: 64co x 256n per CTA, 8 warps (32co x 64n each).
// ---------------------------------------------------------------------------
template <int LAYER, int DT, int PT, int DM, int PM>
__global__ __launch_bounds__(256, 1) void conv_mma_kernel() {
    extern __shared__ __nv_bfloat16 sm[];
    __nv_bfloat16* As = sm;                   // [2][192][AP]
    __nv_bfloat16* Bs = sm + 2 * A_ELEMS;     // [2][64][BP]

    const __nv_bfloat16* __restrict__ in = (LAYER == 2) ? g_s1 : g_s2;
    const __nv_bfloat16* __restrict__ ws = (LAYER == 2) ? g_w2s : g_w3s;

    int b  = blockIdx.y;
    int n0 = blockIdx.x * NT;
    int tid  = threadIdx.x;
    int warp = tid >> 5, lane = tid & 31;
    int wco = (warp >> 2) * 32;      // 0 or 32
    int wn  = (warp & 3) * 64;       // 0/64/128/192

    const __nv_bfloat16* inb = in + (size_t)b * CC * N_SP;

    // B gather: one n column per thread, all 64 ci
    int nl  = tid;
    int ng  = n0 + nl;
    int tt0 = ng / MM;
    int mm0 = ng - tt0 * MM;

    float acc[2][8][4];
#pragma unroll
    for (int i = 0; i < 2; i++)
#pragma unroll
        for (int j = 0; j < 8; j++)
#pragma unroll
            for (int q = 0; q < 4; q++) acc[i][j][q] = 0.f;

    const __nv_bfloat16 BZERO = __float2bfloat16(0.f);

    auto fill = [&](int tap, int sel) {
        const uint4* wsrc = (const uint4*)(ws + (size_t)tap * 3 * CC * CC);
        __nv_bfloat16* Ad = As + sel * A_ELEMS;
#pragma unroll
        for (int r = 0; r < 6; r++) {
            int i = tid + r * 256;
            int row = i >> 3, q = i & 7;
            *(uint4*)(Ad + row * AP + q * 8) = wsrc[i];
        }
        int kt = tap / 3, km = tap - kt * 3;
        int tt = tt0 + DT * kt - PT;
        int mm = mm0 + DM * km - PM;
        bool p = (tt >= 0) & (tt < TT_) & (mm >= 0) & (mm < MM);
        const __nv_bfloat16* src = inb + (tt * MM + mm);
        __nv_bfloat16* Bd = Bs + sel * B_ELEMS + nl;
        if (p) {
#pragma unroll
            for (int c = 0; c < 64; c++) Bd[c * BP] = src[(size_t)c * N_SP];
        } else {
#pragma unroll
            for (int c = 0; c < 64; c++) Bd[c * BP] = BZERO;
        }
    };

    auto domma = [&](int sel) {
        const __nv_bfloat16* Ab = As + sel * A_ELEMS;
        const __nv_bfloat16* Bb = Bs + sel * B_ELEMS;
#pragma unroll
        for (int ks = 0; ks < 4; ks++) {
            int k0 = ks * 16;
            unsigned bf[8][2];
#pragma unroll
            for (int g = 0; g < 4; g++) {
                unsigned addr = smem_u32(Bb + (k0 + (lane & 15)) * BP +
                                         wn + g * 16 + (lane >> 4) * 8);
                unsigned q0, q1, q2, q3;
                ldsm_x4_t(addr, q0, q1, q2, q3);
                bf[2 * g][0] = q0; bf[2 * g][1] = q1;
                bf[2 * g + 1][0] = q2; bf[2 * g + 1][1] = q3;
            }
#pragma unroll
            for (int s = 0; s < 3; s++) {
#pragma unroll
                for (int mf = 0; mf < 2; mf++) {
                    unsigned addr = smem_u32(Ab + (s * 64 + wco + mf * 16 + (lane & 15)) * AP +
                                             k0 + (lane >> 4) * 8);
                    unsigned a[4];
                    ldsm_x4(addr, a[0], a[1], a[2], a[3]);
#pragma unroll
                    for (int nf = 0; nf < 8; nf++)
                        mma16816(acc[mf][nf], a, bf[nf]);
                }
            }
        }
    };

    fill(0, 0);
    __syncthreads();
#pragma unroll
    for (int tap = 0; tap < 12; tap++) {
        domma(tap & 1);
        if (tap < 11) fill(tap + 1, (tap + 1) & 1);
        __syncthreads();
    }

    int lrow = lane >> 2, lk = (lane & 3) * 2;
    float* outb = g_u + (size_t)b * CC * N_SP;
#pragma unroll
    for (int mf = 0; mf < 2; mf++) {
#pragma unroll
        for (int nf = 0; nf < 8; nf++) {
            int co = wco + mf * 16 + lrow;
            int n  = n0 + wn + nf * 8 + lk;
            float* p1 = outb + (size_t)co * N_SP + n;
            float* p2 = outb + (size_t)(co + 8) * N_SP + n;
            if (n + 1 < N_SP) {
                *(float2*)p1 = make_float2(acc[mf][nf][0], acc[mf][nf][1]);
                *(float2*)p2 = make_float2(acc[mf][nf][2], acc[mf][nf][3]);
            } else if (n < N_SP) {
                p1[0] = acc[mf][nf][0];
                p2[0] = acc[mf][nf][2];
            }
        }
    }
}

// ---------------------------------------------------------------------------
// LIF vectorized (4 m per thread). Writes bf16 spikes to g_s2.
// ---------------------------------------------------------------------------
__global__ void lif2_kernel() {
    int idx = blockIdx.x * blockDim.x + threadIdx.x;
    if (idx >= VTHREADS) return;
    int mq = idx % 10;
    int bc = idx / 10;
    const float* up = g_u + (size_t)bc * N_SP + mq * 4;
    __nv_bfloat16* sp = g_s2 + (size_t)bc * N_SP + mq * 4;
    float v0 = 0.f, v1 = 0.f, v2 = 0.f, v3 = 0.f;
    for (int t = 0; t < TT_; t++) {
        float4 u = *(const float4*)(up + t * MM);
        v0 = v0 + (u.x - v0) / TAUF;
        v1 = v1 + (u.y - v1) / TAUF;
        v2 = v2 + (u.z - v2) / TAUF;
        v3 = v3 + (u.w - v3) / TAUF;
        float s0 = (v0 >= 1.f) ? 1.f : 0.f;
        float s1 = (v1 >= 1.f) ? 1.f : 0.f;
        float s2 = (v2 >= 1.f) ? 1.f : 0.f;
        float s3 = (v3 >= 1.f) ? 1.f : 0.f;
        v0 = (v0 >= 1.f) ? 0.f : v0;
        v1 = (v1 >= 1.f) ? 0.f : v1;
        v2 = (v2 >= 1.f) ? 0.f : v2;
        v3 = (v3 >= 1.f) ? 0.f : v3;
        __nv_bfloat162 h01 = __floats2bfloat162_rn(s0, s1);
        __nv_bfloat162 h23 = __floats2bfloat162_rn(s2, s3);
        *(uint2*)(sp + t * MM) = make_uint2(*(unsigned*)&h01, *(unsigned*)&h23);
    }
}

// ---------------------------------------------------------------------------
// LIF3 fused with time-sum: no spike buffer, writes g_ssum directly.
// ---------------------------------------------------------------------------
__global__ void lif3_tsum_kernel() {
    int idx = blockIdx.x * blockDim.x + threadIdx.x;
    if (idx >= VTHREADS) return;
    int mq = idx % 10;
    int bc = idx / 10;
    const float* up = g_u + (size_t)bc * N_SP + mq * 4;
    float v0 = 0.f, v1 = 0.f, v2 = 0.f, v3 = 0.f;
    float a0 = 0.f, a1 = 0.f, a2 = 0.f, a3 = 0.f;
    for (int t = 0; t < TT_; t++) {
        float4 u = *(const float4*)(up + t * MM);
        v0 = v0 + (u.x - v0) / TAUF;
        v1 = v1 + (u.y - v1) / TAUF;
        v2 = v2 + (u.z - v2) / TAUF;
        v3 = v3 + (u.w - v3) / TAUF;
        if (v0 >= 1.f) { a0 += 1.f; v0 = 0.f; }
        if (v1 >= 1.f) { a1 += 1.f; v1 = 0.f; }
        if (v2 >= 1.f) { a2 += 1.f; v2 = 0.f; }
        if (v3 >= 1.f) { a3 += 1.f; v3 = 0.f; }
    }
    *(float4*)(g_ssum + (size_t)bc * MM + mq * 4) = make_float4(a0, a1, a2, a3);
}

// ---------------------------------------------------------------------------
__global__ void fc_kernel(const float* __restrict__ wf,
                          const float* __restrict__ bf,
                          float* __restrict__ y) {
    int b = blockIdx.x, j = blockIdx.y;
    int tid = threadIdx.x;
    const float* sb = g_ssum + b * (CC * MM);
    const float* wj = wf + j * (CC * MM);
    float acc = 0.f;
    for (int i = tid; i < CC * MM; i += 128) acc += sb[i] * wj[i];
    __shared__ float red[128];
    red[tid] = acc;
    __syncthreads();
    for (int s = 64; s > 0; s >>= 1) {
        if (tid < s) red[tid] += red[tid + s];
        __syncthreads();
    }
    if (tid == 0) y[b * 12 + j] = red[0] * (1.0f / 129.0f) + bf[j];
}

// ---------------------------------------------------------------------------
extern "C" void kernel_launch(void* const* d_in, const int* in_sizes, int n_in,
                              void* d_out, int out_size) {
    const float* x  = (const float*)d_in[0];
    const float* w1 = (const float*)d_in[1];
    const float* w2 = (const float*)d_in[2];
    const float* w3 = (const float*)d_in[3];
    const float* wf = (const float*)d_in[4];
    const float* bf = (const float*)d_in[5];
    float* y = (float*)d_out;

    static int smem_set = 0;
    if (!smem_set) {
        cudaFuncSetAttribute(conv_mma_kernel<2, 4, 6, 3, 3>,
                             cudaFuncAttributeMaxDynamicSharedMemorySize, SMEM_BYTES);
        cudaFuncSetAttribute(conv_mma_kernel<3, 16, 24, 9, 9>,
                             cudaFuncAttributeMaxDynamicSharedMemorySize, SMEM_BYTES);
        smem_set = 1;
    }

    wsplit_kernel<<<(CC * CC * 12 + 255) / 256, 256>>>(w2, 0);
    wsplit_kernel<<<(CC * CC * 12 + 255) / 256, 256>>>(w3, 1);

    conv1_lif_kernel<<<(VTHREADS + 255) / 256, 256>>>(x, w1);

    {
        dim3 grid((N_SP + NT - 1) / NT, BB);
        conv_mma_kernel<2, 4, 6, 3, 3><<<grid, 256, SMEM_BYTES>>>();
    }
    lif2_kernel<<<(VTHREADS + 255) / 256, 256>>>();

    {
        dim3 grid((N_SP + NT - 1) / NT, BB);
        conv_mma_kernel<3, 16, 24, 9, 9><<<grid, 256, SMEM_BYTES>>>();
    }
    lif3_tsum_kernel<<<(VTHREADS + 255) / 256, 256>>>();

    {
        dim3 grid(BB, 12);
        fc_kernel<<<grid, 128>>>(wf, bf, y);
    }
}